// round 14
// baseline (speedup 1.0000x reference)
#include <cuda_runtime.h>
#include <cuda_bf16.h>
#include <cstdint>

// CenterLoss: out = mean_b ||features[b] - centers[labels[b]]||^2
// B = 65536, D = 256, C = 100000, LAMBDA_C = 1.0.
//
// R14: cp.async.bulk (UBLKCP) + mbarrier ring. Per stage, ONE lane issues
// TWO 1KB bulk copies (feature row + gathered center row) tracked by a
// per-warp-slot mbarrier (expect_tx 2048B) -- 2 instructions/stage instead
// of 128 per-lane cp.asyncs. Zero register cost, issue-pipe cost ~60x lower,
// in-flight depth = 3 stages x 2KB per warp (DEPTH=4 ring).
// 4 warps/block, 8 rows/warp, 2048 blocks; 32KB smem/block.
// L2 policy: centers evict_last (labels repeat across graph replays ->
// resident; wall < ncu dur confirms), features evict_first (one-pass).
// Block partial -> last-block-done double reduction; wrapping atomic counter
// self-resets across replays. mbarriers re-initialized every launch.

#define D 256
#define ROW_BYTES (D * 4)          // 1024
#define STAGE_BYTES (2 * ROW_BYTES)
#define WARPS_PER_BLOCK 4
#define ROWS_PER_WARP 8
#define NBLOCKS 2048               // 2048 * 4 * 8 = 65536 = B
#define DEPTH 4

__device__ float g_partials[NBLOCKS];
__device__ unsigned int g_ctr = 0;

__device__ __forceinline__ void bulk1k(uint32_t dst_smem, const void* src,
                                       uint32_t mbar, unsigned long long pol) {
    asm volatile(
        "cp.async.bulk.shared::cta.global.mbarrier::complete_tx::bytes.L2::cache_hint "
        "[%0], [%1], %2, [%3], %4;"
        :: "r"(dst_smem), "l"(src), "r"(ROW_BYTES), "r"(mbar), "l"(pol) : "memory");
}

__device__ __forceinline__ void mbar_wait(uint32_t mbar, uint32_t parity) {
    uint32_t done;
    asm volatile(
        "{\n\t.reg .pred p;\n\t"
        "mbarrier.try_wait.parity.acquire.cta.shared::cta.b64 p, [%1], %2;\n\t"
        "selp.b32 %0, 1, 0, p;\n\t}"
        : "=r"(done) : "r"(mbar), "r"(parity) : "memory");
    while (!done) {
        asm volatile(
            "{\n\t.reg .pred p;\n\t"
            "mbarrier.try_wait.parity.acquire.cta.shared::cta.b64 p, [%1], %2, 0x989680;\n\t"
            "selp.b32 %0, 1, 0, p;\n\t}"
            : "=r"(done) : "r"(mbar), "r"(parity) : "memory");
    }
}

__global__ __launch_bounds__(WARPS_PER_BLOCK * 32)
void center_loss_fused(const float* __restrict__ feat,
                       const int* __restrict__ labels,
                       const float* __restrict__ centers,
                       float* __restrict__ out, int B) {
    // Per-warp DEPTH-slot ring: [feat 1KB | center 1KB] per slot.
    __shared__ __align__(16) char cpbuf[WARPS_PER_BLOCK][DEPTH][STAGE_BYTES];
    __shared__ __align__(8) unsigned long long mbar[WARPS_PER_BLOCK][DEPTH];

    const int warp = threadIdx.x >> 5;
    const int lane = threadIdx.x & 31;
    const int row0 = (blockIdx.x * WARPS_PER_BLOCK + warp) * ROWS_PER_WARP;

    // Init this warp's mbarriers (fresh every launch -> parity starts at 0).
    if (lane == 0) {
        #pragma unroll
        for (int d = 0; d < DEPTH; d++) {
            uint32_t mb = (uint32_t)__cvta_generic_to_shared(&mbar[warp][d]);
            asm volatile("mbarrier.init.shared::cta.b64 [%0], 1;" :: "r"(mb) : "memory");
        }
    }
    __syncthreads();   // all barriers visible before any bulk targets them

    unsigned long long pol_last, pol_first;
    asm volatile("createpolicy.fractional.L2::evict_last.b64 %0, 1.0;"  : "=l"(pol_last));
    asm volatile("createpolicy.fractional.L2::evict_first.b64 %0, 1.0;" : "=l"(pol_first));

    // Preload all 8 labels (2 broadcast int4 loads).
    int labs[ROWS_PER_WARP];
    #pragma unroll
    for (int q = 0; q < 2; q++) {
        int4 l4 = *reinterpret_cast<const int4*>(labels + row0 + q * 4);
        labs[q * 4 + 0] = l4.x; labs[q * 4 + 1] = l4.y;
        labs[q * 4 + 2] = l4.z; labs[q * 4 + 3] = l4.w;
    }

    const char* fbase = reinterpret_cast<const char*>(feat) + (size_t)row0 * ROW_BYTES;
    const char* cbase = reinterpret_cast<const char*>(centers);
    const uint32_t sbase = (uint32_t)__cvta_generic_to_shared(&cpbuf[warp][0][0]);
    const uint32_t mbase = (uint32_t)__cvta_generic_to_shared(&mbar[warp][0]);
    const int lo = lane * 16;

    // Lane 0 issues one stage: expect_tx(2KB) + 2x 1KB bulk copy.
    auto issue = [&](int j) {
        if (lane == 0) {
            const int slot = j & (DEPTH - 1);
            const uint32_t mb = mbase + slot * 8;
            const uint32_t dd = sbase + slot * STAGE_BYTES;
            asm volatile("mbarrier.arrive.expect_tx.shared::cta.b64 _, [%0], %1;"
                         :: "r"(mb), "r"(STAGE_BYTES) : "memory");
            bulk1k(dd,             fbase + (size_t)j * ROW_BYTES,          mb, pol_first);
            bulk1k(dd + ROW_BYTES, cbase + (size_t)labs[j] * ROW_BYTES,    mb, pol_last);
        }
    };

    // Prologue: 3 stages in flight.
    issue(0); issue(1); issue(2);

    float acc = 0.0f;
    #pragma unroll
    for (int j = 0; j < ROWS_PER_WARP; j++) {
        const int slot = j & (DEPTH - 1);
        const uint32_t parity = (j / DEPTH) & 1;
        mbar_wait(mbase + slot * 8, parity);

        const char* d = &cpbuf[warp][slot][0];
        float4 a0 = *reinterpret_cast<const float4*>(d + lo);
        float4 a1 = *reinterpret_cast<const float4*>(d + 512 + lo);
        float4 b0 = *reinterpret_cast<const float4*>(d + ROW_BYTES + lo);
        float4 b1 = *reinterpret_cast<const float4*>(d + ROW_BYTES + 512 + lo);
        float t;
        t = a0.x - b0.x; acc = fmaf(t, t, acc);
        t = a0.y - b0.y; acc = fmaf(t, t, acc);
        t = a0.z - b0.z; acc = fmaf(t, t, acc);
        t = a0.w - b0.w; acc = fmaf(t, t, acc);
        t = a1.x - b1.x; acc = fmaf(t, t, acc);
        t = a1.y - b1.y; acc = fmaf(t, t, acc);
        t = a1.z - b1.z; acc = fmaf(t, t, acc);
        t = a1.w - b1.w; acc = fmaf(t, t, acc);

        // All lanes done reading this slot before lane 0 refills it.
        __syncwarp();
        if (j + 3 < ROWS_PER_WARP) issue(j + 3);
    }

    // Warp reduction (fixed tree -> deterministic)
    #pragma unroll
    for (int o = 16; o > 0; o >>= 1)
        acc += __shfl_xor_sync(0xFFFFFFFFu, acc, o);

    __shared__ float s[WARPS_PER_BLOCK];
    __shared__ bool is_last;
    if (lane == 0) s[warp] = acc;
    __syncthreads();

    if (threadIdx.x == 0) {
        float t = 0.0f;
        #pragma unroll
        for (int i = 0; i < WARPS_PER_BLOCK; i++) t += s[i];
        g_partials[blockIdx.x] = t;
        __threadfence();
        unsigned int old = atomicInc(&g_ctr, gridDim.x - 1);  // wraps -> replay-safe
        is_last = (old == gridDim.x - 1);
    }
    __syncthreads();

    if (!is_last) return;

    // Last block: deterministic double-precision reduction of 2048 partials.
    __shared__ double sd[128];
    const volatile float* vp = g_partials;
    double t = 0.0;
    #pragma unroll 4
    for (int i = threadIdx.x; i < NBLOCKS; i += 128)
        t += (double)vp[i];
    sd[threadIdx.x] = t;
    __syncthreads();
    #pragma unroll
    for (int stride = 64; stride > 0; stride >>= 1) {
        if (threadIdx.x < stride) sd[threadIdx.x] += sd[threadIdx.x + stride];
        __syncthreads();
    }
    if (threadIdx.x == 0)
        out[0] = (float)(sd[0] / (double)B);   // LAMBDA_C = 1.0
}

extern "C" void kernel_launch(void* const* d_in, const int* in_sizes, int n_in,
                              void* d_out, int out_size) {
    const float* feat    = (const float*)d_in[0];
    const int*   labels  = (const int*)d_in[1];
    const float* centers = (const float*)d_in[2];
    float*       out     = (float*)d_out;

    const int B = in_sizes[1];   // 65536

    center_loss_fused<<<NBLOCKS, WARPS_PER_BLOCK * 32>>>(feat, labels, centers, out, B);
}

// round 15
// speedup vs baseline: 2.2065x; 2.2065x over previous
#include <cuda_runtime.h>
#include <cuda_bf16.h>
#include <cstdint>

// CenterLoss: out = mean_b ||features[b] - centers[labels[b]]||^2
// B = 65536, D = 256, C = 100000, LAMBDA_C = 1.0.
//
// R15 hybrid (R14's bulk+mbarrier was a 2.4x regression -> reverted to the
// R12 cp.async engine, restructured):
//  - CENTERS (random gather): cp.async per lane (2x16B = 1KB/row/warp) into
//    a DEPTH-4 SMEM ring, 3 stages in flight (wait_group 3). Zero dest regs.
//  - FEATURES (sequential stream): one 256-bit ld.global.nc per row per lane,
//    register double-buffered -- no SMEM staging needed for predictable
//    addresses. Halves smem (51KB -> 33KB/block) -> 6 blocks/SM -> occ
//    toward 100% (R12 was stuck at 45%).
// L2 policy: centers evict_last (labels repeat across graph replays ->
// resident; wall < ncu dur confirms the dividend), features evict_first.
// Block partial -> last-block-done double reduction; wrapping atomic counter
// self-resets across replays.

#define D 256
#define ROW_BYTES (D * 4)          // 1024
#define WARPS_PER_BLOCK 8
#define ROWS_PER_WARP 8
#define NBLOCKS 1024               // 1024 * 8 * 8 = 65536 = B
#define DEPTH 4                    // center ring slots (3 in flight + 1 consuming)

__device__ float g_partials[NBLOCKS];
__device__ unsigned int g_ctr = 0;

struct V8 { unsigned long long u[4]; };

// Streamed 256-bit feature load (evict-first everywhere).
__device__ __forceinline__ V8 ld_stream(const void* p) {
    V8 v;
    asm volatile("ld.global.nc.L1::evict_first.L2::evict_first.v4.b64 {%0,%1,%2,%3}, [%4];"
                 : "=l"(v.u[0]), "=l"(v.u[1]), "=l"(v.u[2]), "=l"(v.u[3]) : "l"(p));
    return v;
}

__device__ __forceinline__ void cp16(uint32_t dst_smem, const void* src, unsigned long long pol) {
    asm volatile("cp.async.cg.shared.global.L2::cache_hint [%0], [%1], 16, %2;"
                 :: "r"(dst_smem), "l"(src), "l"(pol) : "memory");
}

__global__ __launch_bounds__(WARPS_PER_BLOCK * 32)
void center_loss_fused(const float* __restrict__ feat,
                       const int* __restrict__ labels,
                       const float* __restrict__ centers,
                       float* __restrict__ out, int B) {
    // Per-warp DEPTH-slot center ring: 1KB per slot.
    __shared__ __align__(16) char cbuf[WARPS_PER_BLOCK][DEPTH][ROW_BYTES];

    const int warp = threadIdx.x >> 5;
    const int lane = threadIdx.x & 31;
    const int row0 = (blockIdx.x * WARPS_PER_BLOCK + warp) * ROWS_PER_WARP;

    unsigned long long pol_last;
    asm volatile("createpolicy.fractional.L2::evict_last.b64 %0, 1.0;" : "=l"(pol_last));

    // Preload all 8 labels (2 broadcast int4 loads).
    int labs[ROWS_PER_WARP];
    #pragma unroll
    for (int q = 0; q < 2; q++) {
        int4 l4 = *reinterpret_cast<const int4*>(labels + row0 + q * 4);
        labs[q * 4 + 0] = l4.x; labs[q * 4 + 1] = l4.y;
        labs[q * 4 + 2] = l4.z; labs[q * 4 + 3] = l4.w;
    }

    const char* fbase = reinterpret_cast<const char*>(feat) + (size_t)row0 * ROW_BYTES + lane * 32;
    const char* cbase = reinterpret_cast<const char*>(centers);
    const uint32_t sbase = (uint32_t)__cvta_generic_to_shared(&cbuf[warp][0][0]);
    const int lo = lane * 16;

    // Issue center row j into ring slot (j & 3): 2x16B cp.async per lane.
    auto issue_c = [&](int j) {
        const uint32_t d = sbase + (uint32_t)(j & (DEPTH - 1)) * ROW_BYTES;
        const char* cs = cbase + (size_t)labs[j] * ROW_BYTES;
        cp16(d + lo,       cs + lo,       pol_last);
        cp16(d + 512 + lo, cs + 512 + lo, pol_last);
        asm volatile("cp.async.commit_group;" ::: "memory");
    };

    // Prologue: 3 center stages in flight + feature stage 0 in registers.
    issue_c(0); issue_c(1); issue_c(2);
    V8 fbuf[2];
    fbuf[0] = ld_stream(fbase);

    float acc = 0.0f;
    #pragma unroll
    for (int j = 0; j < ROWS_PER_WARP; j++) {
        const int cur = j & 1, nxt = cur ^ 1;
        // Keep the pipe full before waiting.
        if (j + 3 < ROWS_PER_WARP) issue_c(j + 3);
        if (j + 1 < ROWS_PER_WARP) fbuf[nxt] = ld_stream(fbase + (size_t)(j + 1) * ROW_BYTES);

        // Wait for center stage j (compile-time constant group counts).
        if (j + 3 < ROWS_PER_WARP)      { asm volatile("cp.async.wait_group 3;" ::: "memory"); }
        else if (j + 2 < ROWS_PER_WARP) { asm volatile("cp.async.wait_group 2;" ::: "memory"); }
        else if (j + 1 < ROWS_PER_WARP) { asm volatile("cp.async.wait_group 1;" ::: "memory"); }
        else                            { asm volatile("cp.async.wait_group 0;" ::: "memory"); }

        // Consume: lane reads exactly the 2x16B it copied (no cross-lane sync).
        const char* d = &cbuf[warp][j & (DEPTH - 1)][0];
        float4 b0 = *reinterpret_cast<const float4*>(d + lo);
        float4 b1 = *reinterpret_cast<const float4*>(d + 512 + lo);
        const float* a = reinterpret_cast<const float*>(&fbuf[cur]);
        float t;
        t = a[0] - b0.x; acc = fmaf(t, t, acc);
        t = a[1] - b0.y; acc = fmaf(t, t, acc);
        t = a[2] - b0.z; acc = fmaf(t, t, acc);
        t = a[3] - b0.w; acc = fmaf(t, t, acc);
        t = a[4] - b1.x; acc = fmaf(t, t, acc);
        t = a[5] - b1.y; acc = fmaf(t, t, acc);
        t = a[6] - b1.z; acc = fmaf(t, t, acc);
        t = a[7] - b1.w; acc = fmaf(t, t, acc);
    }

    // Warp reduction (fixed tree -> deterministic)
    #pragma unroll
    for (int o = 16; o > 0; o >>= 1)
        acc += __shfl_xor_sync(0xFFFFFFFFu, acc, o);

    __shared__ float s[WARPS_PER_BLOCK];
    __shared__ bool is_last;
    if (lane == 0) s[warp] = acc;
    __syncthreads();

    if (threadIdx.x == 0) {
        float t = 0.0f;
        #pragma unroll
        for (int i = 0; i < WARPS_PER_BLOCK; i++) t += s[i];
        g_partials[blockIdx.x] = t;
        __threadfence();
        unsigned int old = atomicInc(&g_ctr, gridDim.x - 1);  // wraps -> replay-safe
        is_last = (old == gridDim.x - 1);
    }
    __syncthreads();

    if (!is_last) return;

    // Last block: deterministic double-precision reduction of 1024 partials.
    __shared__ double sd[256];
    const volatile float* vp = g_partials;
    double t = 0.0;
    #pragma unroll 4
    for (int i = threadIdx.x; i < NBLOCKS; i += 256)
        t += (double)vp[i];
    sd[threadIdx.x] = t;
    __syncthreads();
    #pragma unroll
    for (int stride = 128; stride > 0; stride >>= 1) {
        if (threadIdx.x < stride) sd[threadIdx.x] += sd[threadIdx.x + stride];
        __syncthreads();
    }
    if (threadIdx.x == 0)
        out[0] = (float)(sd[0] / (double)B);   // LAMBDA_C = 1.0
}

extern "C" void kernel_launch(void* const* d_in, const int* in_sizes, int n_in,
                              void* d_out, int out_size) {
    const float* feat    = (const float*)d_in[0];
    const int*   labels  = (const int*)d_in[1];
    const float* centers = (const float*)d_in[2];
    float*       out     = (float*)d_out;

    const int B = in_sizes[1];   // 65536

    center_loss_fused<<<NBLOCKS, WARPS_PER_BLOCK * 32>>>(feat, labels, centers, out, B);
}